// round 8
// baseline (speedup 1.0000x reference)
#include <cuda_runtime.h>
#include <cuda_fp16.h>

// WordHashing: sparse [B=16384 x 30000] (COO, rows sorted) @ W [30000 x 300] + bias, ReLU.
// R7 post-mortem: spmm latency-bound at occ=49.7% (regs=46 from unroll-8 load
// pipelining), L2 only 44.9% (NOT at cap); 608B row stride misaligns the 512B
// gather (5 lines instead of 4 for 75% of rows).
// R8: split arrays (512B-aligned main + 96B tail), unroll 4 + 256-thread CTAs +
// launch_bounds(256,6) for occupancy, int4-staged {offm, offt, val, val} so one
// LDS.128 yields offsets and pre-packed f32x2 value.

#define OUT_DIM   300
#define IN_DIM    30000
#define MAX_BATCH 16384

#define MAIN_BYTES 512          // 256 halves: cols 0..255
#define TAIL_BYTES 96           // 48 halves: cols 256..303 (300..303 pad)

#define PREP_THREADS 256
#define PREP_ITEMS   (IN_DIM * 38)     // 32 main int4 + 6 tail int4 per row
#define PREP_CONV_BLOCKS ((PREP_ITEMS + PREP_THREADS - 1) / PREP_THREADS)

__device__ int g_row_start[MAX_BATCH + 1];
__device__ __align__(128) int4 g_Wmain4[IN_DIM * 32];   // 15.36 MB
__device__ __align__(128) int4 g_Wtail4[IN_DIM * 6];    //  2.88 MB

// ---------------------------------------------------------------------------
// Fused prep: blocks [0, PREP_CONV_BLOCKS) convert W f32 -> split fp16 arrays;
// remaining blocks build row_start from sorted sp_rows.
__global__ void prep_kernel(const float* __restrict__ W,
                            const int* __restrict__ rows,
                            int nnz, int batch, int conv_blocks_thr) {
    if (blockIdx.x < (unsigned)conv_blocks_thr) {
        const int i = blockIdx.x * PREP_THREADS + threadIdx.x;
        if (i >= PREP_ITEMS) return;
        const int row = i / 38;
        const int k   = i - row * 38;
        const bool is_main = (k < 32);
        const int col = is_main ? (k * 8) : (256 + (k - 32) * 8);

        float4 a = make_float4(0.f, 0.f, 0.f, 0.f);
        float4 b = make_float4(0.f, 0.f, 0.f, 0.f);
        const float4* src = reinterpret_cast<const float4*>(W + (size_t)row * OUT_DIM + col);
        if (col + 8 <= OUT_DIM)      { a = __ldg(src); b = __ldg(src + 1); }
        else if (col < OUT_DIM)      { a = __ldg(src); }   // col==296: cols 296..299

        __align__(16) __half2 hh[4];
        hh[0] = __floats2half2_rn(a.x, a.y);
        hh[1] = __floats2half2_rn(a.z, a.w);
        hh[2] = __floats2half2_rn(b.x, b.y);
        hh[3] = __floats2half2_rn(b.z, b.w);
        const int4 v = *reinterpret_cast<const int4*>(hh);
        if (is_main) g_Wmain4[row * 32 + k]        = v;
        else         g_Wtail4[row * 6 + (k - 32)]  = v;
    } else {
        const int i = (blockIdx.x - conv_blocks_thr) * PREP_THREADS + threadIdx.x;
        if (i >= nnz) return;
        int r  = rows[i];
        int rp = (i == 0) ? -1 : rows[i - 1];
        for (int q = rp + 1; q <= r; ++q) g_row_start[q] = i;
        if (i == nnz - 1) {
            for (int q = r + 1; q <= batch; ++q) g_row_start[q] = nnz;
        }
    }
}

// ---------------------------------------------------------------------------
// Packed convert+FMA: acc(f32x2) += cvt(f16x2 w2) * vv(f32x2).
__device__ __forceinline__ void cvt_fma2(unsigned long long& acc,
                                         unsigned int w2,
                                         unsigned long long vv) {
    asm("{\n\t"
        ".reg .b16 l, h;\n\t"
        ".reg .f32 fl, fh;\n\t"
        ".reg .b64 wp;\n\t"
        "mov.b32 {l, h}, %1;\n\t"
        "cvt.f32.f16 fl, l;\n\t"
        "cvt.f32.f16 fh, h;\n\t"
        "mov.b64 wp, {fl, fh};\n\t"
        "fma.rn.f32x2 %0, wp, %2, %0;\n\t"
        "}" : "+l"(acc) : "r"(w2), "l"(vv));
}

// ---------------------------------------------------------------------------
// spmm: 256-thread CTA = 8 independent warps, one sparse row each.
// Lane t: LDG.128 of main cols [8t, 8t+8); lanes 0..23: LDG.32 of tail cols
// [256+2t, +2). Chunks staged as int4 {c*512, c*96, val, val}; LDS.128 broadcast.
__global__ __launch_bounds__(256, 6) void spmm_row_kernel(
    const int*   __restrict__ cols,
    const float* __restrict__ vals,
    const float* __restrict__ bias,
    float*       __restrict__ out,
    int batch)
{
    __shared__ int4 s_cv[8][2][32];
    const int warp = threadIdx.x >> 5;
    const int lane = threadIdx.x & 31;
    const int row  = blockIdx.x * 8 + warp;
    if (row >= batch) return;

    const int start = g_row_start[row];        // uniform -> broadcast LDG
    const int end   = g_row_start[row + 1];

    unsigned long long a0 = 0ull, a1 = 0ull, a2 = 0ull, a3 = 0ull, a4 = 0ull;

    const char* __restrict__ mbase =
        reinterpret_cast<const char*>(g_Wmain4) + lane * 16;
    const char* __restrict__ tbase =
        reinterpret_cast<const char*>(g_Wtail4) + lane * 4;
    const bool has_tail = (lane < 24);

    // Prefetch chunk 0.
    int4 pf = make_int4(0, 0, 0, 0);
    if (start + lane < end) {
        const int c = __ldg(cols + start + lane);
        const int v = __float_as_int(__ldg(vals + start + lane));
        pf = make_int4(c * MAIN_BYTES, c * TAIL_BYTES, v, v);
    }

    int parity = 0;
    for (int base = start; base < end; base += 32, parity ^= 1) {
        const int rem = end - base;
        const int n   = rem < 32 ? rem : 32;
        s_cv[warp][parity][lane] = pf;         // publish current chunk (STS.128)
        __syncwarp();
        const int nb = base + 32;
        if (nb + lane < end) {                 // prefetch next chunk
            const int c = __ldg(cols + nb + lane);
            const int v = __float_as_int(__ldg(vals + nb + lane));
            pf = make_int4(c * MAIN_BYTES, c * TAIL_BYTES, v, v);
        }
        #pragma unroll 4
        for (int j = 0; j < n; ++j) {
            const ulonglong2 cv =                    // LDS.128 broadcast
                *reinterpret_cast<const ulonglong2*>(&s_cv[warp][parity][j]);
            int offm, offt;
            asm("mov.b64 {%0, %1}, %2;" : "=r"(offm), "=r"(offt) : "l"(cv.x));
            const unsigned long long vv = cv.y;      // pre-packed {v, v}
            const int4 w4 = __ldg(reinterpret_cast<const int4*>(mbase + offm));
            int w1 = 0;
            if (has_tail) w1 = __ldg(reinterpret_cast<const int*>(tbase + offt));
            cvt_fma2(a0, (unsigned)w4.x, vv);
            cvt_fma2(a1, (unsigned)w4.y, vv);
            cvt_fma2(a2, (unsigned)w4.z, vv);
            cvt_fma2(a3, (unsigned)w4.w, vv);
            cvt_fma2(a4, (unsigned)w1,   vv);
        }
    }

    float acc[10];
    asm("mov.b64 {%0, %1}, %2;" : "=f"(acc[0]), "=f"(acc[1]) : "l"(a0));
    asm("mov.b64 {%0, %1}, %2;" : "=f"(acc[2]), "=f"(acc[3]) : "l"(a1));
    asm("mov.b64 {%0, %1}, %2;" : "=f"(acc[4]), "=f"(acc[5]) : "l"(a2));
    asm("mov.b64 {%0, %1}, %2;" : "=f"(acc[6]), "=f"(acc[7]) : "l"(a3));
    asm("mov.b64 {%0, %1}, %2;" : "=f"(acc[8]), "=f"(acc[9]) : "l"(a4));

    // Epilogue: +bias, ReLU, coalesced stores.
    float* orow = out + (size_t)row * OUT_DIM;
    const int c0 = lane * 8;                   // 0..248
    const float4 b0 = __ldg(reinterpret_cast<const float4*>(bias + c0));
    const float4 b1 = __ldg(reinterpret_cast<const float4*>(bias + c0 + 4));
    float4 o0, o1;
    o0.x = fmaxf(acc[0] + b0.x, 0.f);  o0.y = fmaxf(acc[1] + b0.y, 0.f);
    o0.z = fmaxf(acc[2] + b0.z, 0.f);  o0.w = fmaxf(acc[3] + b0.w, 0.f);
    o1.x = fmaxf(acc[4] + b1.x, 0.f);  o1.y = fmaxf(acc[5] + b1.y, 0.f);
    o1.z = fmaxf(acc[6] + b1.z, 0.f);  o1.w = fmaxf(acc[7] + b1.w, 0.f);
    *reinterpret_cast<float4*>(orow + c0)     = o0;
    *reinterpret_cast<float4*>(orow + c0 + 4) = o1;

    const int c1 = 256 + 2 * lane;             // tail cols; valid while < 300
    if (c1 < OUT_DIM) {                        // lanes 0..21
        const float2 b2 = __ldg(reinterpret_cast<const float2*>(bias + c1));
        float2 o2;
        o2.x = fmaxf(acc[8] + b2.x, 0.f);
        o2.y = fmaxf(acc[9] + b2.y, 0.f);
        *reinterpret_cast<float2*>(orow + c1) = o2;
    }
}

extern "C" void kernel_launch(void* const* d_in, const int* in_sizes, int n_in,
                              void* d_out, int out_size) {
    const int*   sp_rows = (const int*)  d_in[0];
    const int*   sp_cols = (const int*)  d_in[1];
    const float* sp_vals = (const float*)d_in[2];
    const float* weights = (const float*)d_in[3];
    const float* bias    = (const float*)d_in[4];

    const int nnz   = in_sizes[0];
    const int batch = out_size / OUT_DIM;

    const int build_blocks = (nnz + PREP_THREADS - 1) / PREP_THREADS;
    prep_kernel<<<PREP_CONV_BLOCKS + build_blocks, PREP_THREADS>>>(
        weights, sp_rows, nnz, batch, PREP_CONV_BLOCKS);
    spmm_row_kernel<<<(batch + 7) / 8, 256>>>(sp_cols, sp_vals, bias,
                                              (float*)d_out, batch);
}

// round 9
// speedup vs baseline: 1.1654x; 1.1654x over previous
#include <cuda_runtime.h>
#include <cuda_fp16.h>

// WordHashing: sparse [B=16384 x 30000] (COO, rows sorted) @ W [30000 x 300] + bias, ReLU.
// R8 post-mortem: occupancy experiment regressed (unroll-4 halved MLP, 8-row CTAs
// lengthened stragglers). R9 = R7 config (128-thr CTAs, unroll 8) + ONLY the
// alignment fix: split W into 512B-aligned main (always 4 lines/gather) + 96B
// tail array. Staging: int4 {c*512, c*96, v, v}, one LDS.128 broadcast.

#define OUT_DIM   300
#define IN_DIM    30000
#define MAX_BATCH 16384

#define MAIN_BYTES 512          // 256 halves: cols 0..255
#define TAIL_BYTES 96           // 48 halves: cols 256..303 (300..303 pad)

#define PREP_THREADS 256
#define PREP_ITEMS   (IN_DIM * 38)     // 32 main int4 + 6 tail int4 per row
#define PREP_CONV_BLOCKS ((PREP_ITEMS + PREP_THREADS - 1) / PREP_THREADS)

__device__ int g_row_start[MAX_BATCH + 1];
__device__ __align__(128) int4 g_Wmain4[IN_DIM * 32];   // 15.36 MB
__device__ __align__(128) int4 g_Wtail4[IN_DIM * 6];    //  2.88 MB

// ---------------------------------------------------------------------------
// Fused prep: blocks [0, PREP_CONV_BLOCKS) convert W f32 -> split fp16 arrays;
// remaining blocks build row_start from sorted sp_rows.
__global__ void prep_kernel(const float* __restrict__ W,
                            const int* __restrict__ rows,
                            int nnz, int batch, int conv_blocks_thr) {
    if (blockIdx.x < (unsigned)conv_blocks_thr) {
        const int i = blockIdx.x * PREP_THREADS + threadIdx.x;
        if (i >= PREP_ITEMS) return;
        const int row = i / 38;
        const int k   = i - row * 38;
        const bool is_main = (k < 32);
        const int col = is_main ? (k * 8) : (256 + (k - 32) * 8);

        float4 a = make_float4(0.f, 0.f, 0.f, 0.f);
        float4 b = make_float4(0.f, 0.f, 0.f, 0.f);
        const float4* src = reinterpret_cast<const float4*>(W + (size_t)row * OUT_DIM + col);
        if (col + 8 <= OUT_DIM)      { a = __ldg(src); b = __ldg(src + 1); }
        else if (col < OUT_DIM)      { a = __ldg(src); }   // col==296: cols 296..299

        __align__(16) __half2 hh[4];
        hh[0] = __floats2half2_rn(a.x, a.y);
        hh[1] = __floats2half2_rn(a.z, a.w);
        hh[2] = __floats2half2_rn(b.x, b.y);
        hh[3] = __floats2half2_rn(b.z, b.w);
        const int4 v = *reinterpret_cast<const int4*>(hh);
        if (is_main) g_Wmain4[row * 32 + k]        = v;
        else         g_Wtail4[row * 6 + (k - 32)]  = v;
    } else {
        const int i = (blockIdx.x - conv_blocks_thr) * PREP_THREADS + threadIdx.x;
        if (i >= nnz) return;
        int r  = rows[i];
        int rp = (i == 0) ? -1 : rows[i - 1];
        for (int q = rp + 1; q <= r; ++q) g_row_start[q] = i;
        if (i == nnz - 1) {
            for (int q = r + 1; q <= batch; ++q) g_row_start[q] = nnz;
        }
    }
}

// ---------------------------------------------------------------------------
// Packed convert+FMA: acc(f32x2) += cvt(f16x2 w2) * vv(f32x2).
__device__ __forceinline__ void cvt_fma2(unsigned long long& acc,
                                         unsigned int w2,
                                         unsigned long long vv) {
    asm("{\n\t"
        ".reg .b16 l, h;\n\t"
        ".reg .f32 fl, fh;\n\t"
        ".reg .b64 wp;\n\t"
        "mov.b32 {l, h}, %1;\n\t"
        "cvt.f32.f16 fl, l;\n\t"
        "cvt.f32.f16 fh, h;\n\t"
        "mov.b64 wp, {fl, fh};\n\t"
        "fma.rn.f32x2 %0, wp, %2, %0;\n\t"
        "}" : "+l"(acc) : "r"(w2), "l"(vv));
}

// ---------------------------------------------------------------------------
// spmm: 128-thread CTA = 4 independent warps, one sparse row each (R7 config).
// Lane t: LDG.128 of main cols [8t,8t+8) (always 4 aligned lines);
// lanes 0..23: LDG.32 of tail cols [256+2t,+2).
__global__ __launch_bounds__(128) void spmm_row_kernel(
    const int*   __restrict__ cols,
    const float* __restrict__ vals,
    const float* __restrict__ bias,
    float*       __restrict__ out,
    int batch)
{
    __shared__ int4 s_cv[4][2][32];
    const int warp = threadIdx.x >> 5;
    const int lane = threadIdx.x & 31;
    const int row  = blockIdx.x * 4 + warp;
    if (row >= batch) return;

    const int start = g_row_start[row];        // uniform -> broadcast LDG
    const int end   = g_row_start[row + 1];

    unsigned long long a0 = 0ull, a1 = 0ull, a2 = 0ull, a3 = 0ull, a4 = 0ull;

    const char* __restrict__ mbase =
        reinterpret_cast<const char*>(g_Wmain4) + lane * 16;
    const char* __restrict__ tbase =
        reinterpret_cast<const char*>(g_Wtail4) + lane * 4;
    const bool has_tail = (lane < 24);

    // Prefetch chunk 0.
    int4 pf = make_int4(0, 0, 0, 0);
    if (start + lane < end) {
        const int c = __ldg(cols + start + lane);
        const int v = __float_as_int(__ldg(vals + start + lane));
        pf = make_int4(c * MAIN_BYTES, c * TAIL_BYTES, v, v);
    }

    int parity = 0;
    for (int base = start; base < end; base += 32, parity ^= 1) {
        const int rem = end - base;
        const int n   = rem < 32 ? rem : 32;
        s_cv[warp][parity][lane] = pf;         // publish current chunk (STS.128)
        __syncwarp();
        const int nb = base + 32;
        if (nb + lane < end) {                 // prefetch next chunk
            const int c = __ldg(cols + nb + lane);
            const int v = __float_as_int(__ldg(vals + nb + lane));
            pf = make_int4(c * MAIN_BYTES, c * TAIL_BYTES, v, v);
        }
        #pragma unroll 8
        for (int j = 0; j < n; ++j) {
            const ulonglong2 cv =                    // LDS.128 broadcast
                *reinterpret_cast<const ulonglong2*>(&s_cv[warp][parity][j]);
            int offm, offt;
            asm("mov.b64 {%0, %1}, %2;" : "=r"(offm), "=r"(offt) : "l"(cv.x));
            const unsigned long long vv = cv.y;      // pre-packed {v, v}
            const int4 w4 = __ldg(reinterpret_cast<const int4*>(mbase + offm));
            int w1 = 0;
            if (has_tail) w1 = __ldg(reinterpret_cast<const int*>(tbase + offt));
            cvt_fma2(a0, (unsigned)w4.x, vv);
            cvt_fma2(a1, (unsigned)w4.y, vv);
            cvt_fma2(a2, (unsigned)w4.z, vv);
            cvt_fma2(a3, (unsigned)w4.w, vv);
            cvt_fma2(a4, (unsigned)w1,   vv);
        }
    }

    float acc[10];
    asm("mov.b64 {%0, %1}, %2;" : "=f"(acc[0]), "=f"(acc[1]) : "l"(a0));
    asm("mov.b64 {%0, %1}, %2;" : "=f"(acc[2]), "=f"(acc[3]) : "l"(a1));
    asm("mov.b64 {%0, %1}, %2;" : "=f"(acc[4]), "=f"(acc[5]) : "l"(a2));
    asm("mov.b64 {%0, %1}, %2;" : "=f"(acc[6]), "=f"(acc[7]) : "l"(a3));
    asm("mov.b64 {%0, %1}, %2;" : "=f"(acc[8]), "=f"(acc[9]) : "l"(a4));

    // Epilogue: +bias, ReLU, coalesced stores.
    float* orow = out + (size_t)row * OUT_DIM;
    const int c0 = lane * 8;                   // 0..248
    const float4 b0 = __ldg(reinterpret_cast<const float4*>(bias + c0));
    const float4 b1 = __ldg(reinterpret_cast<const float4*>(bias + c0 + 4));
    float4 o0, o1;
    o0.x = fmaxf(acc[0] + b0.x, 0.f);  o0.y = fmaxf(acc[1] + b0.y, 0.f);
    o0.z = fmaxf(acc[2] + b0.z, 0.f);  o0.w = fmaxf(acc[3] + b0.w, 0.f);
    o1.x = fmaxf(acc[4] + b1.x, 0.f);  o1.y = fmaxf(acc[5] + b1.y, 0.f);
    o1.z = fmaxf(acc[6] + b1.z, 0.f);  o1.w = fmaxf(acc[7] + b1.w, 0.f);
    *reinterpret_cast<float4*>(orow + c0)     = o0;
    *reinterpret_cast<float4*>(orow + c0 + 4) = o1;

    const int c1 = 256 + 2 * lane;             // tail cols; valid while < 300
    if (c1 < OUT_DIM) {                        // lanes 0..21
        const float2 b2 = __ldg(reinterpret_cast<const float2*>(bias + c1));
        float2 o2;
        o2.x = fmaxf(acc[8] + b2.x, 0.f);
        o2.y = fmaxf(acc[9] + b2.y, 0.f);
        *reinterpret_cast<float2*>(orow + c1) = o2;
    }
}

extern "C" void kernel_launch(void* const* d_in, const int* in_sizes, int n_in,
                              void* d_out, int out_size) {
    const int*   sp_rows = (const int*)  d_in[0];
    const int*   sp_cols = (const int*)  d_in[1];
    const float* sp_vals = (const float*)d_in[2];
    const float* weights = (const float*)d_in[3];
    const float* bias    = (const float*)d_in[4];

    const int nnz   = in_sizes[0];
    const int batch = out_size / OUT_DIM;

    const int build_blocks = (nnz + PREP_THREADS - 1) / PREP_THREADS;
    prep_kernel<<<PREP_CONV_BLOCKS + build_blocks, PREP_THREADS>>>(
        weights, sp_rows, nnz, batch, PREP_CONV_BLOCKS);
    spmm_row_kernel<<<(batch + 3) / 4, 128>>>(sp_cols, sp_vals, bias,
                                              (float*)d_out, batch);
}

// round 10
// speedup vs baseline: 1.1919x; 1.0228x over previous
#include <cuda_runtime.h>
#include <cuda_fp16.h>

// WordHashing: sparse [B=16384 x 30000] (COO, rows sorted) @ W [30000 x 300] + bias, ReLU.
// R9 post-mortem: split-array alignment fix regressed (sector overhead was hidden);
// reverted to R7 layout (608B rows, int2 staging). R10 single change: cvt_fma2 no
// longer wraps half-extraction in asm (which blocked F2F .H0/.H1 selector folding
// and emitted ~10 junk MOVs/nnz) — use __half22float2 intrinsic + asm FFMA2 only.

#define OUT_DIM   300
#define IN_DIM    30000
#define ROW_INT4  38           // 38 x 16B = 608B per padded fp16 row (304 halves)
#define ROW_BYTES 608
#define MAX_BATCH 16384

#define CONV_THREADS 256
#define CONV_BLOCKS  ((IN_DIM * ROW_INT4 + CONV_THREADS - 1) / CONV_THREADS)

__device__ int g_row_start[MAX_BATCH + 1];
__device__ __align__(128) int4 g_Wh4[IN_DIM * ROW_INT4];   // 18.2 MB fp16 staged weights

// ---------------------------------------------------------------------------
// Fused prep: blocks [0, CONV_BLOCKS) convert W f32 -> padded f16 rows;
// remaining blocks build row_start from sorted sp_rows.
__global__ void prep_kernel(const float* __restrict__ W,
                            const int* __restrict__ rows,
                            int nnz, int batch, int conv_blocks_thr) {
    if (blockIdx.x < (unsigned)conv_blocks_thr) {
        const int i = blockIdx.x * CONV_THREADS + threadIdx.x;
        if (i >= IN_DIM * ROW_INT4) return;
        const int row = i / ROW_INT4;
        const int k   = i - row * ROW_INT4;
        const int col = k * 8;

        float4 a = make_float4(0.f, 0.f, 0.f, 0.f);
        float4 b = make_float4(0.f, 0.f, 0.f, 0.f);
        const float4* src = reinterpret_cast<const float4*>(W + (size_t)row * OUT_DIM + col);
        if (col + 8 <= OUT_DIM)      { a = __ldg(src); b = __ldg(src + 1); }
        else if (col < OUT_DIM)      { a = __ldg(src); }   // k==37: cols 296..299

        __align__(16) __half2 hh[4];
        hh[0] = __floats2half2_rn(a.x, a.y);
        hh[1] = __floats2half2_rn(a.z, a.w);
        hh[2] = __floats2half2_rn(b.x, b.y);
        hh[3] = __floats2half2_rn(b.z, b.w);
        g_Wh4[i] = *reinterpret_cast<const int4*>(hh);
    } else {
        const int i = (blockIdx.x - conv_blocks_thr) * CONV_THREADS + threadIdx.x;
        if (i >= nnz) return;
        int r  = rows[i];
        int rp = (i == 0) ? -1 : rows[i - 1];
        for (int q = rp + 1; q <= r; ++q) g_row_start[q] = i;
        if (i == nnz - 1) {
            for (int q = r + 1; q <= batch; ++q) g_row_start[q] = nnz;
        }
    }
}

// ---------------------------------------------------------------------------
// Packed convert+FMA. Conversion via intrinsic so ptxas emits F2F.F32.F16 with
// .H0/.H1 selectors (no MOV scaffolding); only the FFMA2 needs asm.
__device__ __forceinline__ void cvt_fma2(unsigned long long& acc,
                                         unsigned int w2,
                                         unsigned long long vv) {
    __half2 h;
    *reinterpret_cast<unsigned int*>(&h) = w2;
    const float2 wf = __half22float2(h);            // 2x F2F, selector form
    asm("{\n\t"
        ".reg .b64 wp;\n\t"
        "mov.b64 wp, {%1, %2};\n\t"                 // register pairing (alloc-resolved)
        "fma.rn.f32x2 %0, wp, %3, %0;\n\t"
        "}" : "+l"(acc) : "f"(wf.x), "f"(wf.y), "l"(vv));
}

// ---------------------------------------------------------------------------
// spmm: 128-thread CTA = 4 independent warps, one sparse row each (R7 config).
// Lane t owns cols [8t,8t+8) (LDG.128); lanes 0..21 also own cols [256+2t,+2).
// (col,val) chunks staged via smem int2 {c*608, val}, register-prefetched.
__global__ __launch_bounds__(128) void spmm_row_kernel(
    const int*   __restrict__ cols,
    const float* __restrict__ vals,
    const float* __restrict__ bias,
    float*       __restrict__ out,
    int batch)
{
    __shared__ int2 s_cv[4][2][32];
    const int warp = threadIdx.x >> 5;
    const int lane = threadIdx.x & 31;
    const int row  = blockIdx.x * 4 + warp;
    if (row >= batch) return;

    const int start = g_row_start[row];        // uniform -> broadcast LDG
    const int end   = g_row_start[row + 1];

    unsigned long long a0 = 0ull, a1 = 0ull, a2 = 0ull, a3 = 0ull, a4 = 0ull;

    const char* __restrict__ lbase =
        reinterpret_cast<const char*>(g_Wh4) + lane * 16;
    const int tail_imm = 512 - lane * 16 + lane * 4;   // rowp+512+4*lane rel. to lbase
    const bool has_tail = (lane < 22);

    // Prefetch chunk 0.
    int2 pf = make_int2(0, 0);
    if (start + lane < end) {
        pf = make_int2(__ldg(cols + start + lane) * ROW_BYTES,
                       __float_as_int(__ldg(vals + start + lane)));
    }

    int parity = 0;
    for (int base = start; base < end; base += 32, parity ^= 1) {
        const int rem = end - base;
        const int n   = rem < 32 ? rem : 32;
        s_cv[warp][parity][lane] = pf;         // publish current chunk
        __syncwarp();
        const int nb = base + 32;
        if (nb + lane < end) {                 // prefetch next chunk
            pf = make_int2(__ldg(cols + nb + lane) * ROW_BYTES,
                           __float_as_int(__ldg(vals + nb + lane)));
        }
        #pragma unroll 8
        for (int j = 0; j < n; ++j) {
            const int2  cv = s_cv[warp][parity][j];    // LDS.64 broadcast
            const float v  = __int_as_float(cv.y);
            unsigned long long vv;
            asm("mov.b64 %0, {%1, %1};" : "=l"(vv) : "f"(v));
            const char* p = lbase + cv.x;
            const int4 w4 = __ldg(reinterpret_cast<const int4*>(p));
            int w1 = 0;
            if (has_tail) w1 = __ldg(reinterpret_cast<const int*>(p + tail_imm));
            cvt_fma2(a0, (unsigned)w4.x, vv);
            cvt_fma2(a1, (unsigned)w4.y, vv);
            cvt_fma2(a2, (unsigned)w4.z, vv);
            cvt_fma2(a3, (unsigned)w4.w, vv);
            cvt_fma2(a4, (unsigned)w1,   vv);
        }
    }

    float acc[10];
    asm("mov.b64 {%0, %1}, %2;" : "=f"(acc[0]), "=f"(acc[1]) : "l"(a0));
    asm("mov.b64 {%0, %1}, %2;" : "=f"(acc[2]), "=f"(acc[3]) : "l"(a1));
    asm("mov.b64 {%0, %1}, %2;" : "=f"(acc[4]), "=f"(acc[5]) : "l"(a2));
    asm("mov.b64 {%0, %1}, %2;" : "=f"(acc[6]), "=f"(acc[7]) : "l"(a3));
    asm("mov.b64 {%0, %1}, %2;" : "=f"(acc[8]), "=f"(acc[9]) : "l"(a4));

    // Epilogue: +bias, ReLU, coalesced stores.
    float* orow = out + (size_t)row * OUT_DIM;
    const int c0 = lane * 8;                   // 0..248
    const float4 b0 = __ldg(reinterpret_cast<const float4*>(bias + c0));
    const float4 b1 = __ldg(reinterpret_cast<const float4*>(bias + c0 + 4));
    float4 o0, o1;
    o0.x = fmaxf(acc[0] + b0.x, 0.f);  o0.y = fmaxf(acc[1] + b0.y, 0.f);
    o0.z = fmaxf(acc[2] + b0.z, 0.f);  o0.w = fmaxf(acc[3] + b0.w, 0.f);
    o1.x = fmaxf(acc[4] + b1.x, 0.f);  o1.y = fmaxf(acc[5] + b1.y, 0.f);
    o1.z = fmaxf(acc[6] + b1.z, 0.f);  o1.w = fmaxf(acc[7] + b1.w, 0.f);
    *reinterpret_cast<float4*>(orow + c0)     = o0;
    *reinterpret_cast<float4*>(orow + c0 + 4) = o1;

    const int c1 = 256 + 2 * lane;             // tail cols; valid while < 300
    if (c1 < OUT_DIM) {                        // lanes 0..21
        const float2 b2 = __ldg(reinterpret_cast<const float2*>(bias + c1));
        float2 o2;
        o2.x = fmaxf(acc[8] + b2.x, 0.f);
        o2.y = fmaxf(acc[9] + b2.y, 0.f);
        *reinterpret_cast<float2*>(orow + c1) = o2;
    }
}

extern "C" void kernel_launch(void* const* d_in, const int* in_sizes, int n_in,
                              void* d_out, int out_size) {
    const int*   sp_rows = (const int*)  d_in[0];
    const int*   sp_cols = (const int*)  d_in[1];
    const float* sp_vals = (const float*)d_in[2];
    const float* weights = (const float*)d_in[3];
    const float* bias    = (const float*)d_in[4];

    const int nnz   = in_sizes[0];
    const int batch = out_size / OUT_DIM;

    const int build_blocks = (nnz + CONV_THREADS - 1) / CONV_THREADS;
    prep_kernel<<<CONV_BLOCKS + build_blocks, CONV_THREADS>>>(
        weights, sp_rows, nnz, batch, CONV_BLOCKS);
    spmm_row_kernel<<<(batch + 3) / 4, 128>>>(sp_cols, sp_vals, bias,
                                              (float*)d_out, batch);
}